// round 7
// baseline (speedup 1.0000x reference)
#include <cuda_runtime.h>
#include <cuda_fp16.h>
#include <cuda_bf16.h>
#include <stdint.h>

// ---------------- static scratch (no allocation allowed) ----------------
#define N_MAX 100352          // >= N=100000
#define E_MAX 1700000         // >= E=1600000
#define F 128                 // feature dim
#define SA 136                // padded smem row stride (halves)
#define TILE 1024             // scan tile size
#define MAXTILES 128

__device__ __align__(16) static __half g_t1[(size_t)N_MAX * F];  // x@W1 (fp16, unscaled)
__device__ __align__(16) static __half g_h1[(size_t)N_MAX * F];  // relu layer-1 out (fp16)
__device__ __align__(16) static __half g_t2[(size_t)N_MAX * F];  // h1@W2 (fp16, unscaled)
__device__ __align__(16) static float g_dis[N_MAX];
__device__ static int   g_degc[N_MAX];
__device__ static int   g_rowptr[N_MAX + 4];
__device__ static int   g_cursor[N_MAX];
__device__ static int   g_csr[E_MAX];
__device__ static int   g_counts[1024];
__device__ static unsigned long long g_tile_state[MAXTILES];  // (flag<<32)|sum
__device__ static int   g_tile_ctr;
__device__ static int   g_e64;
__device__ static int   g_b64;

// ---------------- kernel 1: dtype detect + zero everything ----------------
// blocks 0,1: detect int64-vs-int32; blocks 2..: zero degc/counts/state/out
__global__ void setup_kernel(const int* __restrict__ e, const int* __restrict__ b,
                             int nwords, float* __restrict__ out, int outw, int n) {
    if (blockIdx.x < 2) {
        __shared__ int any;
        if (threadIdx.x == 0) any = 0;
        __syncthreads();
        const int* a = (blockIdx.x == 0) ? e : b;
        int local = 0;
        for (int i = 1 + 2 * (int)threadIdx.x; i < nwords; i += 2 * (int)blockDim.x)
            local |= a[i];
        if (local) atomicOr(&any, 1);
        __syncthreads();
        if (threadIdx.x == 0) {
            int is64 = (any == 0) ? 1 : 0;
            if (blockIdx.x == 0) g_e64 = is64; else g_b64 = is64;
            if (blockIdx.x == 0) g_tile_ctr = 0;
        }
        if (blockIdx.x == 1) {
            for (int i = threadIdx.x; i < MAXTILES; i += blockDim.x) g_tile_state[i] = 0ull;
            for (int i = threadIdx.x; i < 1024; i += blockDim.x) g_counts[i] = 0;
        }
        return;
    }
    int nb = gridDim.x - 2;
    long long idx = (long long)(blockIdx.x - 2) * blockDim.x + threadIdx.x;
    long long stride = (long long)nb * blockDim.x;
    for (long long i = idx; i < n; i += stride) g_degc[i] = 0;
    for (long long i = idx; i < outw; i += stride) out[i] = 0.f;
}

__device__ __forceinline__ long long load_idx(const void* p, long long i, int is64) {
    if (is64) return ((const long long*)p)[i];
    return (long long)((const int*)p)[i];
}

// ---------------- kernel 2: degree histogram ----------------
__global__ void deg_kernel(const void* __restrict__ edge, int E) {
    int e = blockIdx.x * blockDim.x + threadIdx.x;
    if (e >= E) return;
    long long dst = load_idx(edge, (long long)E + e, g_e64);
    atomicAdd(&g_degc[dst], 1);
}

// ---------------- kernel 3: single-pass scan (decoupled lookback) + dis ----
__global__ void __launch_bounds__(TILE) scan_kernel(int n) {
    __shared__ int sh[TILE];
    __shared__ int s_bid;
    __shared__ int s_prefix;
    int t = threadIdx.x;
    if (t == 0) s_bid = atomicAdd(&g_tile_ctr, 1);
    __syncthreads();
    int bid = s_bid;
    int i = bid * TILE + t;
    int v = (i < n) ? g_degc[i] : 0;
    if (i < n) g_dis[i] = rsqrtf((float)(v + 1));     // +1 self loop
    sh[t] = v;
    __syncthreads();
    for (int off = 1; off < TILE; off <<= 1) {
        int tmp = (t >= off) ? sh[t - off] : 0;
        __syncthreads();
        sh[t] += tmp;
        __syncthreads();
    }
    int total = sh[TILE - 1];
    if (t == 0) {
        if (bid == 0) {
            atomicExch(&g_tile_state[0], (2ull << 32) | (unsigned)total);
            s_prefix = 0;
        } else {
            atomicExch(&g_tile_state[bid], (1ull << 32) | (unsigned)total);
            int prefix = 0;
            int j = bid - 1;
            while (j >= 0) {
                unsigned long long st = atomicAdd(&g_tile_state[j], 0ull);
                unsigned flag = (unsigned)(st >> 32);
                if (flag == 2u) { prefix += (int)(unsigned)st; break; }
                if (flag == 1u) { prefix += (int)(unsigned)st; j--; }
                // flag==0: spin
            }
            atomicExch(&g_tile_state[bid], (2ull << 32) | (unsigned)(prefix + total));
            s_prefix = prefix;
        }
    }
    __syncthreads();
    int prefix = s_prefix;
    if (i < n) {
        int r = prefix + sh[t] - v;   // global exclusive
        g_rowptr[i] = r;
        g_cursor[i] = r;
        if (i == n - 1) g_rowptr[n] = r + v;
    }
}

// ---------------- kernel 4: CSR fill ----------------
__global__ void fill_kernel(const void* __restrict__ edge, int E) {
    int e = blockIdx.x * blockDim.x + threadIdx.x;
    if (e >= E) return;
    int is64 = g_e64;
    long long src = load_idx(edge, e, is64);
    long long dst = load_idx(edge, (long long)E + e, is64);
    int p = atomicAdd(&g_cursor[dst], 1);
    g_csr[p] = (int)src;
}

// ---------------- tensor-core GEMM: C = fp16(A @ W), unscaled ----------------
template<bool A_IS_HALF>
__global__ void __launch_bounds__(256) gemm_mma_kernel(
    const void* __restrict__ Aptr, const float* __restrict__ W,
    __half* __restrict__ C, int n)
{
    extern __shared__ __half sh[];
    __half* As = sh;                 // [128][SA]
    __half* Wt = sh + 128 * SA;      // [128][SA] transposed

    int t = threadIdx.x;
    int row0 = blockIdx.x * 128;

    for (int i = t; i < F * F; i += 256) {
        int k = i >> 7, nn = i & 127;
        Wt[nn * SA + k] = __float2half(__ldg(&W[i]));
    }

    if (A_IS_HALF) {
        const __half* A = (const __half*)Aptr;
        for (int i = t; i < 128 * F / 8; i += 256) {
            int lin = i * 8;
            int r = lin >> 7, c = lin & 127;
            uint4 v = make_uint4(0u, 0u, 0u, 0u);
            if (row0 + r < n) v = *(const uint4*)&A[(size_t)(row0 + r) * F + c];
            *(uint4*)&As[r * SA + c] = v;
        }
    } else {
        const float* A = (const float*)Aptr;
        for (int i = t; i < 128 * F / 4; i += 256) {
            int lin = i * 4;
            int r = lin >> 7, c = lin & 127;
            float4 v = make_float4(0.f, 0.f, 0.f, 0.f);
            if (row0 + r < n) v = *(const float4*)&A[(size_t)(row0 + r) * F + c];
            *(__half2*)&As[r * SA + c]     = __floats2half2_rn(v.x, v.y);
            *(__half2*)&As[r * SA + c + 2] = __floats2half2_rn(v.z, v.w);
        }
    }
    __syncthreads();

    int w = t >> 5, lane = t & 31;
    int gq = lane >> 2, tq = lane & 3;
    int m0 = w * 16;

    float acc[16][4];
#pragma unroll
    for (int nt = 0; nt < 16; nt++)
#pragma unroll
        for (int c = 0; c < 4; c++) acc[nt][c] = 0.f;

#pragma unroll
    for (int k0 = 0; k0 < F; k0 += 16) {
        uint32_t a0 = *(const uint32_t*)&As[(m0 + gq) * SA + k0 + tq * 2];
        uint32_t a1 = *(const uint32_t*)&As[(m0 + gq + 8) * SA + k0 + tq * 2];
        uint32_t a2 = *(const uint32_t*)&As[(m0 + gq) * SA + k0 + tq * 2 + 8];
        uint32_t a3 = *(const uint32_t*)&As[(m0 + gq + 8) * SA + k0 + tq * 2 + 8];
#pragma unroll
        for (int nt = 0; nt < 16; nt++) {
            uint32_t b0 = *(const uint32_t*)&Wt[(nt * 8 + gq) * SA + k0 + tq * 2];
            uint32_t b1 = *(const uint32_t*)&Wt[(nt * 8 + gq) * SA + k0 + tq * 2 + 8];
            asm volatile(
                "mma.sync.aligned.m16n8k16.row.col.f32.f16.f16.f32 "
                "{%0,%1,%2,%3}, {%4,%5,%6,%7}, {%8,%9}, {%0,%1,%2,%3};"
                : "+f"(acc[nt][0]), "+f"(acc[nt][1]), "+f"(acc[nt][2]), "+f"(acc[nt][3])
                : "r"(a0), "r"(a1), "r"(a2), "r"(a3), "r"(b0), "r"(b1));
        }
    }

    int r1 = row0 + m0 + gq;
    int r2 = r1 + 8;
#pragma unroll
    for (int nt = 0; nt < 16; nt++) {
        int col = nt * 8 + tq * 2;
        if (r1 < n) *(__half2*)&C[(size_t)r1 * F + col] = __floats2half2_rn(acc[nt][0], acc[nt][1]);
        if (r2 < n) *(__half2*)&C[(size_t)r2 * F + col] = __floats2half2_rn(acc[nt][2], acc[nt][3]);
    }
}

// ---------------- CSR gather: 16-lane group per node, uint4 per lane -------
// acc[8] += dis[src] * t[src][l*8 .. l*8+8)
__device__ __forceinline__ void acc_row(float* acc, uint4 u, float d) {
    float2 f;
    f = __half22float2(*(const __half2*)&u.x); acc[0] += f.x * d; acc[1] += f.y * d;
    f = __half22float2(*(const __half2*)&u.y); acc[2] += f.x * d; acc[3] += f.y * d;
    f = __half22float2(*(const __half2*)&u.z); acc[4] += f.x * d; acc[5] += f.y * d;
    f = __half22float2(*(const __half2*)&u.w); acc[6] += f.x * d; acc[7] += f.y * d;
}

__device__ __forceinline__ void agg_row16(const uint4* __restrict__ gp,
                                          int node, int l, float* acc) {
    uint4 u = __ldg(&gp[(size_t)node * 16 + l]);      // self loop
    float dn = __ldg(&g_dis[node]);
#pragma unroll
    for (int c = 0; c < 8; c++) acc[c] = 0.f;
    acc_row(acc, u, dn);
    int i = g_rowptr[node];
    int end = g_rowptr[node + 1];
    for (; i + 4 <= end; i += 4) {
        int s0 = __ldg(&g_csr[i + 0]);
        int s1 = __ldg(&g_csr[i + 1]);
        int s2 = __ldg(&g_csr[i + 2]);
        int s3 = __ldg(&g_csr[i + 3]);
        float d0 = __ldg(&g_dis[s0]);
        float d1 = __ldg(&g_dis[s1]);
        float d2 = __ldg(&g_dis[s2]);
        float d3 = __ldg(&g_dis[s3]);
        uint4 u0 = __ldg(&gp[(size_t)s0 * 16 + l]);
        uint4 u1 = __ldg(&gp[(size_t)s1 * 16 + l]);
        uint4 u2 = __ldg(&gp[(size_t)s2 * 16 + l]);
        uint4 u3 = __ldg(&gp[(size_t)s3 * 16 + l]);
        acc_row(acc, u0, d0);
        acc_row(acc, u1, d1);
        acc_row(acc, u2, d2);
        acc_row(acc, u3, d3);
    }
    for (; i < end; i++) {
        int s0 = __ldg(&g_csr[i]);
        float d0 = __ldg(&g_dis[s0]);
        uint4 u0 = __ldg(&gp[(size_t)s0 * 16 + l]);
        acc_row(acc, u0, d0);
    }
}

// kernel 6: h1 = fp16(relu(dis*sum + b));  16-lane group per node
__global__ void __launch_bounds__(256) agg1_kernel(const float* __restrict__ b, int n) {
    int grp = (blockIdx.x * blockDim.x + threadIdx.x) >> 4;
    int l = threadIdx.x & 15;
    if (grp >= n) return;
    float acc[8];
    agg_row16((const uint4*)g_t1, grp, l, acc);
    float d = g_dis[grp];
    float4 b0 = __ldg((const float4*)&b[l * 8]);
    float4 b1 = __ldg((const float4*)&b[l * 8 + 4]);
    float o0 = fmaxf(fmaf(d, acc[0], b0.x), 0.f);
    float o1 = fmaxf(fmaf(d, acc[1], b0.y), 0.f);
    float o2 = fmaxf(fmaf(d, acc[2], b0.z), 0.f);
    float o3 = fmaxf(fmaf(d, acc[3], b0.w), 0.f);
    float o4 = fmaxf(fmaf(d, acc[4], b1.x), 0.f);
    float o5 = fmaxf(fmaf(d, acc[5], b1.y), 0.f);
    float o6 = fmaxf(fmaf(d, acc[6], b1.z), 0.f);
    float o7 = fmaxf(fmaf(d, acc[7], b1.w), 0.f);
    __half2 p0 = __floats2half2_rn(o0, o1);
    __half2 p1 = __floats2half2_rn(o2, o3);
    __half2 p2 = __floats2half2_rn(o4, o5);
    __half2 p3 = __floats2half2_rn(o6, o7);
    uint4 st;
    st.x = *(uint32_t*)&p0; st.y = *(uint32_t*)&p1;
    st.z = *(uint32_t*)&p2; st.w = *(uint32_t*)&p3;
    ((uint4*)g_h1)[(size_t)grp * 16 + l] = st;
}

// kernel 8: o = relu(dis*sum + b); mean-pool scatter
__global__ void __launch_bounds__(256) agg2_kernel(
    const void* __restrict__ batch, const float* __restrict__ b,
    float* __restrict__ out, int n)
{
    int grp = (blockIdx.x * blockDim.x + threadIdx.x) >> 4;
    int l = threadIdx.x & 15;
    if (grp >= n) return;
    float acc[8];
    agg_row16((const uint4*)g_t2, grp, l, acc);
    float d = g_dis[grp];
    float4 b0 = __ldg((const float4*)&b[l * 8]);
    float4 b1 = __ldg((const float4*)&b[l * 8 + 4]);
    float o0 = fmaxf(fmaf(d, acc[0], b0.x), 0.f);
    float o1 = fmaxf(fmaf(d, acc[1], b0.y), 0.f);
    float o2 = fmaxf(fmaf(d, acc[2], b0.z), 0.f);
    float o3 = fmaxf(fmaf(d, acc[3], b0.w), 0.f);
    float o4 = fmaxf(fmaf(d, acc[4], b1.x), 0.f);
    float o5 = fmaxf(fmaf(d, acc[5], b1.y), 0.f);
    float o6 = fmaxf(fmaf(d, acc[6], b1.z), 0.f);
    float o7 = fmaxf(fmaf(d, acc[7], b1.w), 0.f);
    long long gid = load_idx(batch, grp, g_b64);
    float* p = &out[(size_t)gid * F + l * 8];
    asm volatile("red.global.add.v4.f32 [%0], {%1,%2,%3,%4};"
                 :: "l"(p), "f"(o0), "f"(o1), "f"(o2), "f"(o3) : "memory");
    asm volatile("red.global.add.v4.f32 [%0], {%1,%2,%3,%4};"
                 :: "l"(p + 4), "f"(o4), "f"(o5), "f"(o6), "f"(o7) : "memory");
    if (l == 0) atomicAdd(&g_counts[gid], 1);
}

// kernel 9: divide by counts
__global__ void div_kernel(float* __restrict__ out, int gtot) {
    int i = blockIdx.x * blockDim.x + threadIdx.x;
    if (i >= gtot * F) return;
    int gidx = i >> 7;
    float cnt = (float)max(g_counts[gidx], 1);
    out[i] = out[i] / cnt;
}

// ---------------- launch ----------------
extern "C" void kernel_launch(void* const* d_in, const int* in_sizes, int n_in,
                              void* d_out, int out_size) {
    const float* x    = (const float*)d_in[0];
    const void*  edge = d_in[1];
    const void*  batch= d_in[2];
    const float* W1   = (const float*)d_in[3];
    const float* b1   = (const float*)d_in[4];
    const float* W2   = (const float*)d_in[5];
    const float* b2   = (const float*)d_in[6];
    float* out = (float*)d_out;

    int N = in_sizes[0] / F;
    int E = in_sizes[1] / 2;
    int G = out_size / F;

    void *p_t1, *p_h1, *p_t2;
    cudaGetSymbolAddress(&p_t1, g_t1);
    cudaGetSymbolAddress(&p_h1, g_h1);
    cudaGetSymbolAddress(&p_t2, g_t2);

    const int SMEM = 2 * 128 * SA * (int)sizeof(__half);   // 69632 bytes
    cudaFuncSetAttribute(gemm_mma_kernel<false>, cudaFuncAttributeMaxDynamicSharedMemorySize, SMEM);
    cudaFuncSetAttribute(gemm_mma_kernel<true>,  cudaFuncAttributeMaxDynamicSharedMemorySize, SMEM);

    const int TB = 256;
    int gemm_grid = (N + 127) / 128;
    int agg_grid = (N + 15) / 16;          // 16 nodes per 256-thread block
    int nblk = (N + TILE - 1) / TILE;

    // 1: detect + zero     2: deg     3: scan(+dis)     4: fill
    setup_kernel<<<2 + 192, TB>>>((const int*)edge, (const int*)batch, 2048, out, G * F, N);
    deg_kernel<<<(E + TB - 1) / TB, TB>>>(edge, E);
    scan_kernel<<<nblk, TILE>>>(N);
    fill_kernel<<<(E + TB - 1) / TB, TB>>>(edge, E);

    // 5: gemm1   6: agg1 (ncu -s 5 profiles this)   7: gemm2   8: agg2   9: div
    gemm_mma_kernel<false><<<gemm_grid, 256, SMEM>>>(x, W1, (__half*)p_t1, N);
    agg1_kernel<<<agg_grid, TB>>>(b1, N);
    gemm_mma_kernel<true><<<gemm_grid, 256, SMEM>>>(p_h1, W2, (__half*)p_t2, N);
    agg2_kernel<<<agg_grid, TB>>>(batch, b2, out, N);
    div_kernel<<<(G * F + TB - 1) / TB, TB>>>(out, G);
}